// round 3
// baseline (speedup 1.0000x reference)
#include <cuda_runtime.h>
#include <cstdint>

#define TT 256

// ---------------- static device scratch (allocation-free) ----------------
__device__ float g_Wc0[768 * 2048];    // enc0 combined: [x | sig_c | eh0] -> gates
__device__ float g_Wc1[1024 * 2048];   // enc1 combined: [eh0 | eh1]
__device__ float g_Wc2[640 * 2048];    // dec0 combined: [z | dh0 | pad]
__device__ float g_Wc3[1024 * 2048];   // dec1 combined: [dh0 | dh1]
__device__ float g_Wms[512 * 128];     // [mu_W | sig_W]
__device__ float g_Wout[512 * 128];    // out_W (tf32 rounded)
__device__ float g_part[8 * 128 * 2048];  // split-K partials
__device__ float g_Ae0[128 * 768];     // A enc0: [xt(128) | sig_c(128) | eh0(512)]
__device__ float g_Ae1[128 * 1024];    // A enc1: [eh0 | eh1]
__device__ float g_Ad0[128 * 640];     // A dec0: [z(64) | dh0(512) | pad(64)]
__device__ float g_Ad1[128 * 1024];    // A dec1: [dh0 | dh1]
__device__ float g_eh1[128 * 512];     // A for mu/sig gemm
__device__ float g_dh1[128 * 512];     // A for out gemm
__device__ float g_ec0[128 * 512];
__device__ float g_ec1[128 * 512];
__device__ float g_dc0[128 * 512];
__device__ float g_dc1[128 * 512];
__device__ unsigned g_barctr;
__device__ unsigned g_bargen;

// ---------------- helpers ----------------
__device__ __forceinline__ float tf32r(float x) {
    unsigned u;
    asm("cvt.rna.tf32.f32 %0, %1;" : "=r"(u) : "f"(x));
    return __uint_as_float(u);
}
__device__ __forceinline__ float sigmf(float x) { return 1.0f / (1.0f + __expf(-x)); }

__device__ __forceinline__ void mma8(float* c, const unsigned* a, const unsigned* b) {
    asm volatile(
        "mma.sync.aligned.m16n8k8.row.col.f32.tf32.tf32.f32 "
        "{%0,%1,%2,%3}, {%4,%5,%6,%7}, {%8,%9}, {%0,%1,%2,%3};\n"
        : "+f"(c[0]), "+f"(c[1]), "+f"(c[2]), "+f"(c[3])
        : "r"(a[0]), "r"(a[1]), "r"(a[2]), "r"(a[3]), "r"(b[0]), "r"(b[1]));
}

// grid-wide barrier: all 128 CTAs co-resident (1 per SM). release/acquire generation.
__device__ __forceinline__ void gbar(unsigned& lgen) {
    __syncthreads();
    ++lgen;
    if (threadIdx.x == 0) {
        __threadfence();
        unsigned old = atomicAdd(&g_barctr, 1u);
        if (old == gridDim.x - 1) {
            g_barctr = 0;
            asm volatile("st.release.gpu.u32 [%0], %1;" ::"l"(&g_bargen), "r"(lgen) : "memory");
        } else {
            unsigned g;
            do {
                asm volatile("ld.acquire.gpu.u32 %0, [%1];" : "=r"(g) : "l"(&g_bargen) : "memory");
                if (g < lgen) __nanosleep(64);
            } while (g < lgen);
        }
    }
    __syncthreads();
}

// ---------------- GEMM unit: C[0:128][n0:n0+NTW] partial over K-tile kt (128 wide) ----
// A row-major [128][lda], W row-major [K][ldw]. Writes g_part[kt].
template <int NTW>
__device__ __forceinline__ void gemm_tile(const float* __restrict__ A, int lda,
                                          const float* __restrict__ W, int ldw,
                                          int kt, int n0, float* sA, float* sB) {
    const int tid = threadIdx.x;
    const int lane = tid & 31;
    const int warp = tid >> 5;
    const int mg = (warp & 3) * 32;
    const int ng = (warp >> 2) * (NTW / 2);
    constexpr int NT = NTW / 16;
    float acc[2][NT][4];
#pragma unroll
    for (int a = 0; a < 2; a++)
#pragma unroll
        for (int b = 0; b < NT; b++)
#pragma unroll
            for (int c = 0; c < 4; c++) acc[a][b][c] = 0.f;

    const float* Ab = A + kt * 128;
    const float* Wb = W + (size_t)(kt * 128) * ldw + n0;

#pragma unroll 1
    for (int kc = 0; kc < 4; ++kc) {
        // stage A chunk: 128 rows x 32 k (L2-fresh via ldcg; written by other SMs)
        {
            int r = tid >> 1, c0 = (tid & 1) * 16;
            const float* src = Ab + (size_t)r * lda + kc * 32 + c0;
            float* dst = sA + r * 36 + c0;
#pragma unroll
            for (int i = 0; i < 4; ++i)
                *(float4*)(dst + i * 4) = __ldcg((const float4*)(src + i * 4));
        }
        // stage W chunk: 32 k x NTW n (read-only weights; L1 ok)
        {
            int r = tid >> 3, c0 = (tid & 7) * (NTW / 8);
            const float* src = Wb + (size_t)(kc * 32 + r) * ldw + c0;
            float* dst = sB + r * 132 + c0;
#pragma unroll
            for (int i = 0; i < NTW / 32; ++i)
                *(float4*)(dst + i * 4) = __ldg((const float4*)(src + i * 4));
        }
        __syncthreads();
#pragma unroll
        for (int ks = 0; ks < 4; ++ks) {
            const int kb = ks * 8;
            unsigned af[2][4];
#pragma unroll
            for (int mt = 0; mt < 2; ++mt) {
                int row = mg + mt * 16 + (lane >> 2);
                int k = kb + (lane & 3);
                af[mt][0] = __float_as_uint(sA[row * 36 + k]);
                af[mt][1] = __float_as_uint(sA[(row + 8) * 36 + k]);
                af[mt][2] = __float_as_uint(sA[row * 36 + k + 4]);
                af[mt][3] = __float_as_uint(sA[(row + 8) * 36 + k + 4]);
            }
#pragma unroll
            for (int nt = 0; nt < NT; ++nt) {
                unsigned bf[2];
                int col = ng + nt * 8 + (lane >> 2);
                bf[0] = __float_as_uint(sB[(kb + (lane & 3)) * 132 + col]);
                bf[1] = __float_as_uint(sB[(kb + 4 + (lane & 3)) * 132 + col]);
                mma8(acc[0][nt], af[0], bf);
                mma8(acc[1][nt], af[1], bf);
            }
        }
        __syncthreads();
    }
    float* C = g_part + (size_t)kt * (128 * 2048) + n0;
#pragma unroll
    for (int mt = 0; mt < 2; ++mt)
#pragma unroll
        for (int nt = 0; nt < NT; ++nt) {
            int row = mg + mt * 16 + (lane >> 2);
            int col = ng + nt * 8 + (lane & 3) * 2;
            C[(size_t)row * 2048 + col] = acc[mt][nt][0];
            C[(size_t)row * 2048 + col + 1] = acc[mt][nt][1];
            C[(size_t)(row + 8) * 2048 + col] = acc[mt][nt][2];
            C[(size_t)(row + 8) * 2048 + col + 1] = acc[mt][nt][3];
        }
}

// reduce split-K partials + LSTM pointwise. CTA r handles batch row r.
__device__ __forceinline__ void lstm_point(int nsplit, const float* __restrict__ b,
                                           float* cst, float* dst1, int ld1,
                                           float* dst2, int ld2) {
    const int r = blockIdx.x;
    for (int j = threadIdx.x; j < 512; j += 256) {
        float gi = b[j], gf = b[512 + j], gc = b[1024 + j], go = b[1536 + j];
        for (int s = 0; s < nsplit; ++s) {
            const float* p = g_part + (size_t)s * 262144 + (size_t)r * 2048;
            gi += __ldcg(p + j);
            gf += __ldcg(p + 512 + j);
            gc += __ldcg(p + 1024 + j);
            go += __ldcg(p + 1536 + j);
        }
        float iv = sigmf(gi), fv = sigmf(gf), ov = sigmf(go), cg = tanhf(gc);
        float c2 = fv * cst[r * 512 + j] + iv * cg;
        cst[r * 512 + j] = c2;
        float h = tf32r(ov * tanhf(c2));
        dst1[r * ld1 + j] = h;
        dst2[r * ld2 + j] = h;
    }
}

// ---------------- init: build combined tf32 weights + initial state ----------------
__global__ void init_kernel(const float* __restrict__ x, const float* __restrict__ e0W,
                            const float* __restrict__ e0U, const float* __restrict__ e1W,
                            const float* __restrict__ e1U, const float* __restrict__ muW,
                            const float* __restrict__ sgW, const float* __restrict__ d0W,
                            const float* __restrict__ d0U, const float* __restrict__ d1W,
                            const float* __restrict__ d1U, const float* __restrict__ oW) {
    size_t id = (size_t)blockIdx.x * blockDim.x + threadIdx.x;
    size_t st = (size_t)gridDim.x * blockDim.x;
    for (size_t i = id; i < 768u * 2048u; i += st) {
        int r = (int)(i >> 11), n = (int)(i & 2047);
        float v;
        if (r < 128) v = e0W[(size_t)r * 2048 + n] + e0W[(size_t)(r + 128) * 2048 + n];
        else if (r < 256) v = -e0W[(size_t)r * 2048 + n];
        else v = e0U[(size_t)(r - 256) * 2048 + n];
        g_Wc0[i] = tf32r(v);
    }
    for (size_t i = id; i < 1024u * 2048u; i += st) {
        int r = (int)(i >> 11), n = (int)(i & 2047);
        float v = (r < 512) ? e1W[(size_t)r * 2048 + n] : e1U[(size_t)(r - 512) * 2048 + n];
        g_Wc1[i] = tf32r(v);
    }
    for (size_t i = id; i < 640u * 2048u; i += st) {
        int r = (int)(i >> 11), n = (int)(i & 2047);
        float v = 0.f;
        if (r < 64) v = d0W[(size_t)r * 2048 + n];
        else if (r < 576) v = d0U[(size_t)(r - 64) * 2048 + n];
        g_Wc2[i] = tf32r(v);
    }
    for (size_t i = id; i < 1024u * 2048u; i += st) {
        int r = (int)(i >> 11), n = (int)(i & 2047);
        float v = (r < 512) ? d1W[(size_t)r * 2048 + n] : d1U[(size_t)(r - 512) * 2048 + n];
        g_Wc3[i] = tf32r(v);
    }
    for (size_t i = id; i < 512u * 128u; i += st) {
        int r = (int)(i >> 7), c = (int)(i & 127);
        float v = (c < 64) ? muW[(size_t)r * 64 + c] : sgW[(size_t)r * 64 + (c - 64)];
        g_Wms[i] = tf32r(v);
    }
    for (size_t i = id; i < 512u * 128u; i += st) g_Wout[i] = tf32r(oW[i]);
    // A_enc0: [xt(t=0) | sigmoid(0)=0.5 | eh0=0]
    for (size_t i = id; i < 128u * 768u; i += st) {
        int r = (int)(i / 768), c = (int)(i % 768);
        float v;
        if (c < 128) v = tf32r(x[(size_t)r * TT * 128 + c]);
        else if (c < 256) v = 0.5f;
        else v = 0.f;
        g_Ae0[i] = v;
    }
    for (size_t i = id; i < 128u * 1024u; i += st) g_Ae1[i] = 0.f;
    for (size_t i = id; i < 128u * 640u; i += st) g_Ad0[i] = 0.f;
    for (size_t i = id; i < 128u * 1024u; i += st) g_Ad1[i] = 0.f;
    for (size_t i = id; i < 128u * 512u; i += st) {
        g_ec0[i] = 0.f; g_ec1[i] = 0.f; g_dc0[i] = 0.f; g_dc1[i] = 0.f;
        g_eh1[i] = 0.f; g_dh1[i] = 0.f;
    }
    if (id == 0) { g_barctr = 0; g_bargen = 0; }
}

// ---------------- persistent kernel: the full 256-step recurrence ----------------
__global__ void __launch_bounds__(256, 1)
vae_kernel(const float* __restrict__ x, const float* __restrict__ eps,
           const float* __restrict__ e0b, const float* __restrict__ e1b,
           const float* __restrict__ mub, const float* __restrict__ sgb,
           const float* __restrict__ d0b, const float* __restrict__ d1b,
           const float* __restrict__ ob, float* __restrict__ out) {
    __shared__ float sA[128 * 36];
    __shared__ float sB[32 * 132];
    unsigned lgen = 0;
    const int cta = blockIdx.x;
    const int tid = threadIdx.x;

    float* dec_o = out;                  // [B,T,D]
    float* sig_o = out + 4194304;        // [T,B,Z]
    float* mu_o  = out + 6291456;
    float* ls_o  = out + 8388608;
    float* z_o   = out + 10485760;

    for (int t = 0; t < TT; ++t) {
        // P0: enc0 GEMM — A=[xt|sig_c|eh0] (768) -> 6 K-tiles x 16 N-tiles = 96 units
        if (cta < 96) gemm_tile<128>(g_Ae0, 768, g_Wc0, 2048, cta >> 4, (cta & 15) << 7, sA, sB);
        gbar(lgen);
        // P1: reduce(6) + LSTM enc0 -> eh0 (into A_enc1[:,0:512] and A_enc0[:,256:768])
        lstm_point(6, e0b, g_ec0, g_Ae1, 1024, g_Ae0 + 256, 768);
        gbar(lgen);
        // P2: enc1 GEMM — 8 x 16 = 128 units
        gemm_tile<128>(g_Ae1, 1024, g_Wc1, 2048, cta >> 4, (cta & 15) << 7, sA, sB);
        gbar(lgen);
        // P3: reduce(8) + LSTM enc1 -> eh1 (g_eh1 and A_enc1[:,512:1024])
        lstm_point(8, e1b, g_ec1, g_eh1, 512, g_Ae1 + 512, 1024);
        gbar(lgen);
        // P4: mu/sig GEMM — K=512: 4 K-tiles x 2 N-halves(64) = 8 units
        if (cta < 8) gemm_tile<64>(g_eh1, 512, g_Wms, 128, cta >> 1, (cta & 1) * 64, sA, sB);
        gbar(lgen);
        // P5: reduce(4) + z = mu + exp(ls)*eps; emit mu/ls/sig/z outputs; build A_dec0 z slot
        if (tid < 64) {
            int r = cta;
            float mu = mub[tid], ls = sgb[tid];
            for (int s = 0; s < 4; ++s) {
                const float* p = g_part + (size_t)s * 262144 + (size_t)r * 2048;
                mu += __ldcg(p + tid);
                ls += __ldcg(p + 64 + tid);
            }
            float sg = expf(ls);
            size_t o = ((size_t)t * 128 + r) * 64 + tid;
            float z = mu + sg * eps[o];
            mu_o[o] = mu; ls_o[o] = ls; sig_o[o] = sg; z_o[o] = z;
            g_Ad0[r * 640 + tid] = tf32r(z);
        }
        gbar(lgen);
        // P6: dec0 GEMM — A=[z|dh0|pad] (640) -> 5 x 16 = 80 units
        if (cta < 80) gemm_tile<128>(g_Ad0, 640, g_Wc2, 2048, cta >> 4, (cta & 15) << 7, sA, sB);
        gbar(lgen);
        // P7: reduce(5) + LSTM dec0 -> dh0 (A_dec1[:,0:512] and A_dec0[:,64:576])
        lstm_point(5, d0b, g_dc0, g_Ad1, 1024, g_Ad0 + 64, 640);
        gbar(lgen);
        // P8: dec1 GEMM — 128 units
        gemm_tile<128>(g_Ad1, 1024, g_Wc3, 2048, cta >> 4, (cta & 15) << 7, sA, sB);
        gbar(lgen);
        // P9: reduce(8) + LSTM dec1 -> dh1 (g_dh1 and A_dec1[:,512:1024])
        lstm_point(8, d1b, g_dc1, g_dh1, 512, g_Ad1 + 512, 1024);
        gbar(lgen);
        // P10: out GEMM — K=512: 8 units
        if (cta < 8) gemm_tile<64>(g_dh1, 512, g_Wout, 128, cta >> 1, (cta & 1) * 64, sA, sB);
        gbar(lgen);
        // P11: reduce(4) + sigmoid -> c_t; store decoded; prep next step's A_enc0
        if (tid < 128) {
            int r = cta;
            float g = ob[tid];
            for (int s = 0; s < 4; ++s)
                g += __ldcg(g_part + (size_t)s * 262144 + (size_t)r * 2048 + tid);
            float c = sigmf(g);
            dec_o[((size_t)r * TT + t) * 128 + tid] = c;
            g_Ae0[r * 768 + 128 + tid] = tf32r(sigmf(c));   // sigmoid(c_prev) for next step
            if (t + 1 < TT)
                g_Ae0[r * 768 + tid] = tf32r(x[((size_t)r * TT + (t + 1)) * 128 + tid]);
        }
        gbar(lgen);
    }
}

extern "C" void kernel_launch(void* const* d_in, const int* in_sizes, int n_in,
                              void* d_out, int out_size) {
    const float* x = (const float*)d_in[0];
    const float* eps = (const float*)d_in[1];
    init_kernel<<<512, 256>>>(x, (const float*)d_in[2], (const float*)d_in[3],
                              (const float*)d_in[5], (const float*)d_in[6],
                              (const float*)d_in[8], (const float*)d_in[10],
                              (const float*)d_in[12], (const float*)d_in[13],
                              (const float*)d_in[15], (const float*)d_in[16],
                              (const float*)d_in[18]);
    vae_kernel<<<128, 256>>>(x, eps, (const float*)d_in[4], (const float*)d_in[7],
                             (const float*)d_in[9], (const float*)d_in[11],
                             (const float*)d_in[14], (const float*)d_in[17],
                             (const float*)d_in[19], (float*)d_out);
}

// round 9
// speedup vs baseline: 1.1151x; 1.1151x over previous
#include <cuda_runtime.h>
#include <cstdint>

#define TT 256

// ---------------- static device scratch (allocation-free) ----------------
__device__ float g_Wc0[768 * 2048];    // enc0 combined: [x | sig_c | eh0] -> gates (tf32)
__device__ float g_Wc1[1024 * 2048];   // enc1 combined: [eh0 | eh1]
__device__ float g_Wc2[640 * 2048];    // dec0 combined: [z | dh0 | pad]
__device__ float g_Wc3[1024 * 2048];   // dec1 combined: [dh0 | dh1]
__device__ float g_WmsT[128 * 512];    // [mu_W | sig_W]^T  (col-major => per-output-contig)
__device__ float g_WoutT[128 * 512];   // out_W^T
__device__ float g_part[8 * 128 * 2048];  // split-K partials
__device__ float g_Ae0[128 * 768];     // A enc0: [xt(128) | sig_c(128) | eh0(512)]
__device__ float g_Ae1[128 * 1024];    // A enc1: [eh0 | eh1]
__device__ float g_Ad0[128 * 640];     // A dec0: [z(64) | dh0(512) | pad(64)]
__device__ float g_Ad1[128 * 1024];    // A dec1: [dh0 | dh1]
__device__ float g_eh1[128 * 512];
__device__ float g_dh1[128 * 512];
__device__ float g_ec0[128 * 512];
__device__ float g_ec1[128 * 512];
__device__ float g_dc0[128 * 512];
__device__ float g_dc1[128 * 512];
__device__ unsigned g_barctr;
__device__ unsigned g_bargen;

// ---------------- helpers ----------------
__device__ __forceinline__ float tf32r(float x) {
    unsigned u;
    asm("cvt.rna.tf32.f32 %0, %1;" : "=r"(u) : "f"(x));
    return __uint_as_float(u);
}
__device__ __forceinline__ float sigmf(float x) { return 1.0f / (1.0f + __expf(-x)); }
__device__ __forceinline__ unsigned fu(float x) { return __float_as_uint(x); }

__device__ __forceinline__ void mma8(float* c, const unsigned* a, const unsigned* b) {
    asm volatile(
        "mma.sync.aligned.m16n8k8.row.col.f32.tf32.tf32.f32 "
        "{%0,%1,%2,%3}, {%4,%5,%6,%7}, {%8,%9}, {%0,%1,%2,%3};\n"
        : "+f"(c[0]), "+f"(c[1]), "+f"(c[2]), "+f"(c[3])
        : "r"(a[0]), "r"(a[1]), "r"(a[2]), "r"(a[3]), "r"(b[0]), "r"(b[1]));
}

__device__ __forceinline__ void cpa_cg(float* sdst, const float* gsrc) {
    unsigned s = (unsigned)__cvta_generic_to_shared(sdst);
    asm volatile("cp.async.cg.shared.global [%0], [%1], 16;" ::"r"(s), "l"(gsrc));
}
__device__ __forceinline__ void cpa_ca(float* sdst, const float* gsrc) {
    unsigned s = (unsigned)__cvta_generic_to_shared(sdst);
    asm volatile("cp.async.ca.shared.global [%0], [%1], 16;" ::"r"(s), "l"(gsrc));
}
#define CPA_COMMIT() asm volatile("cp.async.commit_group;")
#define CPA_WAIT(n) asm volatile("cp.async.wait_group %0;" ::"n"(n))

// grid-wide barrier: 128 CTAs, all co-resident (1 per SM).
__device__ __forceinline__ void gbar(unsigned& lgen) {
    __syncthreads();
    ++lgen;
    if (threadIdx.x == 0) {
        __threadfence();
        unsigned old = atomicAdd(&g_barctr, 1u);
        if (old == gridDim.x - 1) {
            g_barctr = 0;
            asm volatile("st.release.gpu.u32 [%0], %1;" ::"l"(&g_bargen), "r"(lgen) : "memory");
        } else {
            unsigned g;
            do {
                asm volatile("ld.acquire.gpu.u32 %0, [%1];" : "=r"(g) : "l"(&g_bargen) : "memory");
                if (g < lgen) __nanosleep(32);
            } while (g < lgen);
        }
    }
    __syncthreads();
}

// ---------------- GEMM unit: 128x128 partial over K-tile kt; 512 threads ----------------
// A row-major [128][lda] (mutable, L2 via cp.async.cg), W row-major [K][2048] (static, .ca)
// smem: sA 128x132, sB 2 x 32x136
__device__ __forceinline__ void gemm_tile(const float* __restrict__ A, int lda,
                                          const float* __restrict__ W,
                                          int kt, int n0, float* sm) {
    float* sA = sm;
    float* sB = sm + 128 * 132;
    const int tid = threadIdx.x;
    const int lane = tid & 31;
    const int wid = tid >> 5;
    const int mg = (wid & 3) * 32;
    const int ng = (wid >> 2) * 32;
    float acc[2][4][4];
#pragma unroll
    for (int a = 0; a < 2; a++)
#pragma unroll
        for (int b = 0; b < 4; b++)
#pragma unroll
            for (int c = 0; c < 4; c++) acc[a][b][c] = 0.f;

    {   // full A K-tile: 128x128
        int r = tid >> 2, c0 = (tid & 3) * 32;
        const float* src = A + (size_t)r * lda + kt * 128 + c0;
        float* dst = sA + r * 132 + c0;
#pragma unroll
        for (int i = 0; i < 8; ++i) cpa_cg(dst + i * 4, src + i * 4);
    }
    CPA_COMMIT();
    {   // B chunk 0: 32x128
        int r = tid >> 4, c0 = (tid & 15) * 8;
        const float* src = W + (size_t)(kt * 128 + r) * 2048 + n0 + c0;
        float* dst = sB + r * 136 + c0;
        cpa_ca(dst, src);
        cpa_ca(dst + 4, src + 4);
    }
    CPA_COMMIT();

#pragma unroll
    for (int kc = 0; kc < 4; ++kc) {
        if (kc < 3) {
            int r = tid >> 4, c0 = (tid & 15) * 8;
            const float* src = W + (size_t)(kt * 128 + (kc + 1) * 32 + r) * 2048 + n0 + c0;
            float* dst = sB + ((kc + 1) & 1) * (32 * 136) + r * 136 + c0;
            cpa_ca(dst, src);
            cpa_ca(dst + 4, src + 4);
            CPA_COMMIT();
            CPA_WAIT(1);
        } else {
            CPA_WAIT(0);
        }
        __syncthreads();
        const float* sBb = sB + (kc & 1) * (32 * 136);
#pragma unroll
        for (int ks = 0; ks < 4; ++ks) {
            const int kb = kc * 32 + ks * 8;
            unsigned af[2][4];
#pragma unroll
            for (int mt = 0; mt < 2; ++mt) {
                int row = mg + mt * 16 + (lane >> 2);
                int k = kb + (lane & 3);
                af[mt][0] = fu(sA[row * 132 + k]);
                af[mt][1] = fu(sA[(row + 8) * 132 + k]);
                af[mt][2] = fu(sA[row * 132 + k + 4]);
                af[mt][3] = fu(sA[(row + 8) * 132 + k + 4]);
            }
#pragma unroll
            for (int nt = 0; nt < 4; ++nt) {
                int col = ng + nt * 8 + (lane >> 2);
                int rr = ks * 8 + (lane & 3);
                unsigned bf[2];
                bf[0] = fu(sBb[rr * 136 + col]);
                bf[1] = fu(sBb[(rr + 4) * 136 + col]);
                mma8(acc[0][nt], af[0], bf);
                mma8(acc[1][nt], af[1], bf);
            }
        }
        __syncthreads();
    }
    float* C = g_part + (size_t)kt * 262144 + n0;
#pragma unroll
    for (int mt = 0; mt < 2; ++mt)
#pragma unroll
        for (int nt = 0; nt < 4; ++nt) {
            int row = mg + mt * 16 + (lane >> 2);
            int col = ng + nt * 8 + (lane & 3) * 2;
            *(float2*)(C + (size_t)row * 2048 + col) = make_float2(acc[mt][nt][0], acc[mt][nt][1]);
            *(float2*)(C + (size_t)(row + 8) * 2048 + col) = make_float2(acc[mt][nt][2], acc[mt][nt][3]);
        }
}

// reduce split-K partials + LSTM pointwise. CTA r handles batch row r. 512 threads -> j=tid.
__device__ __forceinline__ void lstm_point(int nsplit, const float* __restrict__ b,
                                           float* cst, float* dst1, int ld1,
                                           float* dst2, int ld2) {
    const int r = blockIdx.x;
    const int j = threadIdx.x;
    float gi = b[j], gf = b[512 + j], gc = b[1024 + j], go = b[1536 + j];
    for (int s = 0; s < nsplit; ++s) {
        const float* p = g_part + (size_t)s * 262144 + (size_t)r * 2048;
        gi += __ldcg(p + j);
        gf += __ldcg(p + 512 + j);
        gc += __ldcg(p + 1024 + j);
        go += __ldcg(p + 1536 + j);
    }
    float iv = sigmf(gi), fv = sigmf(gf), ov = sigmf(go), cg = tanhf(gc);
    float c2 = fv * cst[r * 512 + j] + iv * cg;
    cst[r * 512 + j] = c2;
    float h = tf32r(ov * tanhf(c2));
    dst1[r * ld1 + j] = h;
    dst2[r * ld2 + j] = h;
}

// ---------------- init ----------------
__global__ void init_kernel(const float* __restrict__ x, const float* __restrict__ e0W,
                            const float* __restrict__ e0U, const float* __restrict__ e1W,
                            const float* __restrict__ e1U, const float* __restrict__ muW,
                            const float* __restrict__ sgW, const float* __restrict__ d0W,
                            const float* __restrict__ d0U, const float* __restrict__ d1W,
                            const float* __restrict__ d1U, const float* __restrict__ oW) {
    size_t id = (size_t)blockIdx.x * blockDim.x + threadIdx.x;
    size_t st = (size_t)gridDim.x * blockDim.x;
    for (size_t i = id; i < 768u * 2048u; i += st) {
        int r = (int)(i >> 11), n = (int)(i & 2047);
        float v;
        if (r < 128) v = e0W[(size_t)r * 2048 + n] + e0W[(size_t)(r + 128) * 2048 + n];
        else if (r < 256) v = -e0W[(size_t)r * 2048 + n];
        else v = e0U[(size_t)(r - 256) * 2048 + n];
        g_Wc0[i] = tf32r(v);
    }
    for (size_t i = id; i < 1024u * 2048u; i += st) {
        int r = (int)(i >> 11), n = (int)(i & 2047);
        float v = (r < 512) ? e1W[(size_t)r * 2048 + n] : e1U[(size_t)(r - 512) * 2048 + n];
        g_Wc1[i] = tf32r(v);
    }
    for (size_t i = id; i < 640u * 2048u; i += st) {
        int r = (int)(i >> 11), n = (int)(i & 2047);
        float v = 0.f;
        if (r < 64) v = d0W[(size_t)r * 2048 + n];
        else if (r < 576) v = d0U[(size_t)(r - 64) * 2048 + n];
        g_Wc2[i] = tf32r(v);
    }
    for (size_t i = id; i < 1024u * 2048u; i += st) {
        int r = (int)(i >> 11), n = (int)(i & 2047);
        float v = (r < 512) ? d1W[(size_t)r * 2048 + n] : d1U[(size_t)(r - 512) * 2048 + n];
        g_Wc3[i] = tf32r(v);
    }
    // transposed small-layer weights, full fp32
    for (size_t i = id; i < 128u * 512u; i += st) {
        int c = (int)(i >> 9), k = (int)(i & 511);
        g_WmsT[i] = (c < 64) ? muW[(size_t)k * 64 + c] : sgW[(size_t)k * 64 + (c - 64)];
        g_WoutT[i] = oW[(size_t)k * 128 + c];
    }
    // A_enc0: [xt(t=0) | sigmoid(0)=0.5 | eh0=0]
    for (size_t i = id; i < 128u * 768u; i += st) {
        int r = (int)(i / 768), c = (int)(i % 768);
        float v;
        if (c < 128) v = tf32r(x[(size_t)r * TT * 128 + c]);
        else if (c < 256) v = 0.5f;
        else v = 0.f;
        g_Ae0[i] = v;
    }
    for (size_t i = id; i < 128u * 1024u; i += st) { g_Ae1[i] = 0.f; g_Ad1[i] = 0.f; }
    for (size_t i = id; i < 128u * 640u; i += st) g_Ad0[i] = 0.f;
    for (size_t i = id; i < 128u * 512u; i += st) {
        g_ec0[i] = 0.f; g_ec1[i] = 0.f; g_dc0[i] = 0.f; g_dc1[i] = 0.f;
        g_eh1[i] = 0.f; g_dh1[i] = 0.f;
    }
    if (id == 0) { g_barctr = 0; g_bargen = 0; }
}

// ---------------- persistent kernel ----------------
__global__ void __launch_bounds__(512, 1)
vae_kernel(const float* __restrict__ x, const float* __restrict__ eps,
           const float* __restrict__ e0b, const float* __restrict__ e1b,
           const float* __restrict__ mub, const float* __restrict__ sgb,
           const float* __restrict__ d0b, const float* __restrict__ d1b,
           const float* __restrict__ ob, float* __restrict__ out) {
    extern __shared__ float sm[];
    unsigned lgen = 0;
    const int cta = blockIdx.x;
    const int tid = threadIdx.x;
    const int lane = tid & 31;
    const int wid = tid >> 5;

    float* dec_o = out;                  // [B,T,D]
    float* sig_o = out + 4194304;        // [T,B,Z]
    float* mu_o  = out + 6291456;
    float* ls_o  = out + 8388608;
    float* z_o   = out + 10485760;

    for (int t = 0; t < TT; ++t) {
        // P0: enc0 GEMM (96 units)
        if (cta < 96) gemm_tile(g_Ae0, 768, g_Wc0, cta >> 4, (cta & 15) << 7, sm);
        gbar(lgen);
        // P1: reduce(6)+LSTM enc0 -> eh0
        lstm_point(6, e0b, g_ec0, g_Ae1, 1024, g_Ae0 + 256, 768);
        gbar(lgen);
        // P2: enc1 GEMM (128 units)
        gemm_tile(g_Ae1, 1024, g_Wc1, cta >> 4, (cta & 15) << 7, sm);
        gbar(lgen);
        // P3: reduce(8)+LSTM enc1 -> eh1
        lstm_point(8, e1b, g_ec1, g_eh1, 512, g_Ae1 + 512, 1024);
        gbar(lgen);
        // P4: mu/sig FFMA + z-sample (all CTAs; 16-row x 8-col blocks, quad split-K)
        {
            const int rg = cta >> 4, g = cta & 15;
            const int ksub = lane & 3, cl = lane >> 2;   // cl 0..7
            const int r = rg * 16 + wid;                 // one row per warp
            const int cidx = g * 4 + (cl & 3);           // 0..63
            const bool is_sig = cl >= 4;
            const int colw = is_sig ? 64 + cidx : cidx;
            const float* e = g_eh1 + r * 512 + ksub * 128;
            const float* w = g_WmsT + colw * 512 + ksub * 128;
            float acc = 0.f;
#pragma unroll 8
            for (int i = 0; i < 32; ++i) {
                float4 ev = __ldcg((const float4*)(e + i * 4));
                float4 wv = __ldg((const float4*)(w + i * 4));
                acc = fmaf(ev.x, wv.x, acc);
                acc = fmaf(ev.y, wv.y, acc);
                acc = fmaf(ev.z, wv.z, acc);
                acc = fmaf(ev.w, wv.w, acc);
            }
            acc += __shfl_xor_sync(0xffffffffu, acc, 1);
            acc += __shfl_xor_sync(0xffffffffu, acc, 2);
            float other = __shfl_xor_sync(0xffffffffu, acc, 16);
            if (!is_sig && ksub == 0) {
                float mu = acc + mub[cidx];
                float ls = other + sgb[cidx];
                float sg = expf(ls);
                size_t o = ((size_t)t * 128 + r) * 64 + cidx;
                float z = mu + sg * eps[o];
                mu_o[o] = mu; ls_o[o] = ls; sig_o[o] = sg; z_o[o] = z;
                g_Ad0[r * 640 + cidx] = tf32r(z);
            }
        }
        gbar(lgen);
        // P5: dec0 GEMM (80 units)
        if (cta < 80) gemm_tile(g_Ad0, 640, g_Wc2, cta >> 4, (cta & 15) << 7, sm);
        gbar(lgen);
        // P6: reduce(5)+LSTM dec0 -> dh0
        lstm_point(5, d0b, g_dc0, g_Ad1, 1024, g_Ad0 + 64, 640);
        gbar(lgen);
        // P7: dec1 GEMM (128 units)
        gemm_tile(g_Ad1, 1024, g_Wc3, cta >> 4, (cta & 15) << 7, sm);
        gbar(lgen);
        // P8: reduce(8)+LSTM dec1 -> dh1
        lstm_point(8, d1b, g_dc1, g_dh1, 512, g_Ad1 + 512, 1024);
        gbar(lgen);
        // P9: out dense FFMA + sigmoid + outputs + next-step A prep (all CTAs)
        {
            const int rg = cta >> 4, g = cta & 15;
            const int ksub = lane & 3, cl = lane >> 2;
            const int r = rg * 16 + wid;
            const int col = g * 8 + cl;                  // 0..127
            const float* e = g_dh1 + r * 512 + ksub * 128;
            const float* w = g_WoutT + col * 512 + ksub * 128;
            float acc = 0.f;
#pragma unroll 8
            for (int i = 0; i < 32; ++i) {
                float4 ev = __ldcg((const float4*)(e + i * 4));
                float4 wv = __ldg((const float4*)(w + i * 4));
                acc = fmaf(ev.x, wv.x, acc);
                acc = fmaf(ev.y, wv.y, acc);
                acc = fmaf(ev.z, wv.z, acc);
                acc = fmaf(ev.w, wv.w, acc);
            }
            acc += __shfl_xor_sync(0xffffffffu, acc, 1);
            acc += __shfl_xor_sync(0xffffffffu, acc, 2);
            if (ksub == 0) {
                float cv = sigmf(acc + ob[col]);
                dec_o[((size_t)r * TT + t) * 128 + col] = cv;
                g_Ae0[r * 768 + 128 + col] = tf32r(sigmf(cv));
                if (t + 1 < TT)
                    g_Ae0[r * 768 + col] = tf32r(x[((size_t)r * TT + (t + 1)) * 128 + col]);
            }
        }
        gbar(lgen);
    }
}

extern "C" void kernel_launch(void* const* d_in, const int* in_sizes, int n_in,
                              void* d_out, int out_size) {
    const float* x = (const float*)d_in[0];
    const float* eps = (const float*)d_in[1];
    const int smem_bytes = (128 * 132 + 2 * 32 * 136) * 4;  // 102400
    cudaFuncSetAttribute(vae_kernel, cudaFuncAttributeMaxDynamicSharedMemorySize, smem_bytes);
    init_kernel<<<512, 256>>>(x, (const float*)d_in[2], (const float*)d_in[3],
                              (const float*)d_in[5], (const float*)d_in[6],
                              (const float*)d_in[8], (const float*)d_in[10],
                              (const float*)d_in[12], (const float*)d_in[13],
                              (const float*)d_in[15], (const float*)d_in[16],
                              (const float*)d_in[18]);
    vae_kernel<<<128, 512, smem_bytes>>>(x, eps, (const float*)d_in[4], (const float*)d_in[7],
                                         (const float*)d_in[9], (const float*)d_in[11],
                                         (const float*)d_in[14], (const float*)d_in[17],
                                         (const float*)d_in[19], (float*)d_out);
}

// round 12
// speedup vs baseline: 1.1792x; 1.0575x over previous
#include <cuda_runtime.h>
#include <cstdint>

#define TT 256

// ---------------- static device scratch (allocation-free) ----------------
__device__ float g_Wc0[768 * 2048];    // enc0 combined: [x | sig_c | eh0] -> gates (tf32)
__device__ float g_Wc1[1024 * 2048];   // enc1 combined: [eh0 | eh1]
__device__ float g_Wc2[640 * 2048];    // dec0 combined: [z | dh0 | pad]
__device__ float g_Wc3[1024 * 2048];   // dec1 combined: [dh0 | dh1]
__device__ float g_WmsT[128 * 512];    // [mu_W | sig_W]^T  (col-major => per-output-contig)
__device__ float g_WoutT[128 * 512];   // out_W^T
__device__ float g_part[8 * 128 * 2048];  // split-K partials
__device__ float g_Ae0[128 * 768];     // A enc0: [xt(128) | sig_c(128) | eh0(512)]
__device__ float g_Ae1[128 * 1024];    // A enc1: [eh0 | eh1]
__device__ float g_Ad0[128 * 640];     // A dec0: [z(64) | dh0(512) | pad(64)]
__device__ float g_Ad1[128 * 1024];    // A dec1: [dh0 | dh1]
__device__ float g_eh1[128 * 512];
__device__ float g_dh1[128 * 512];
__device__ float g_ec0[128 * 512];
__device__ float g_ec1[128 * 512];
__device__ float g_dc0[128 * 512];
__device__ float g_dc1[128 * 512];
__device__ unsigned g_barctr;

// ---------------- helpers ----------------
__device__ __forceinline__ float tf32r(float x) {
    unsigned u;
    asm("cvt.rna.tf32.f32 %0, %1;" : "=r"(u) : "f"(x));
    return __uint_as_float(u);
}
__device__ __forceinline__ float sigmf(float x) { return 1.0f / (1.0f + __expf(-x)); }
__device__ __forceinline__ unsigned fu(float x) { return __float_as_uint(x); }

__device__ __forceinline__ void mma8(float* c, const unsigned* a, const unsigned* b) {
    asm volatile(
        "mma.sync.aligned.m16n8k8.row.col.f32.tf32.tf32.f32 "
        "{%0,%1,%2,%3}, {%4,%5,%6,%7}, {%8,%9}, {%0,%1,%2,%3};\n"
        : "+f"(c[0]), "+f"(c[1]), "+f"(c[2]), "+f"(c[3])
        : "r"(a[0]), "r"(a[1]), "r"(a[2]), "r"(a[3]), "r"(b[0]), "r"(b[1]));
}

__device__ __forceinline__ void cpa_cg(float* sdst, const float* gsrc) {
    unsigned s = (unsigned)__cvta_generic_to_shared(sdst);
    asm volatile("cp.async.cg.shared.global [%0], [%1], 16;" ::"r"(s), "l"(gsrc));
}
__device__ __forceinline__ void cpa_ca(float* sdst, const float* gsrc) {
    unsigned s = (unsigned)__cvta_generic_to_shared(sdst);
    asm volatile("cp.async.ca.shared.global [%0], [%1], 16;" ::"r"(s), "l"(gsrc));
}
#define CPA_COMMIT() asm volatile("cp.async.commit_group;")
#define CPA_WAIT(n) asm volatile("cp.async.wait_group %0;" ::"n"(n))

// grid-wide barrier: 128 CTAs, all co-resident (1 per SM).
// Arrival: fire-and-forget red.release (no return-value wait, no single-address
// atomic RMW round trip charged to the arriver). Wait: acquire-poll on the
// monotonic counter vs lgen*128. No nanosleep (poll self-paces at L2 latency).
// init_kernel zeroes g_barctr each launch, so graph replays are correct.
__device__ __forceinline__ void gbar(unsigned& lgen) {
    __syncthreads();
    ++lgen;
    if (threadIdx.x == 0) {
        __threadfence();
        asm volatile("red.release.gpu.global.add.u32 [%0], 1;" ::"l"(&g_barctr) : "memory");
        const unsigned target = lgen * 128u;
        unsigned g;
        do {
            asm volatile("ld.acquire.gpu.global.u32 %0, [%1];" : "=r"(g) : "l"(&g_barctr) : "memory");
        } while ((int)(g - target) < 0);
    }
    __syncthreads();
}

// ---------------- GEMM unit: 128x128 partial over K-tile kt; 512 threads ----------------
// A row-major [128][lda] (mutable, L2 via cp.async.cg), W row-major [K][2048] (static, .ca)
// smem: sA 128x132, sB 2 x 32x136
__device__ __forceinline__ void gemm_tile(const float* __restrict__ A, int lda,
                                          const float* __restrict__ W,
                                          int kt, int n0, float* sm) {
    float* sA = sm;
    float* sB = sm + 128 * 132;
    const int tid = threadIdx.x;
    const int lane = tid & 31;
    const int wid = tid >> 5;
    const int mg = (wid & 3) * 32;
    const int ng = (wid >> 2) * 32;
    float acc[2][4][4];
#pragma unroll
    for (int a = 0; a < 2; a++)
#pragma unroll
        for (int b = 0; b < 4; b++)
#pragma unroll
            for (int c = 0; c < 4; c++) acc[a][b][c] = 0.f;

    {   // full A K-tile: 128x128
        int r = tid >> 2, c0 = (tid & 3) * 32;
        const float* src = A + (size_t)r * lda + kt * 128 + c0;
        float* dst = sA + r * 132 + c0;
#pragma unroll
        for (int i = 0; i < 8; ++i) cpa_cg(dst + i * 4, src + i * 4);
    }
    CPA_COMMIT();
    {   // B chunk 0: 32x128
        int r = tid >> 4, c0 = (tid & 15) * 8;
        const float* src = W + (size_t)(kt * 128 + r) * 2048 + n0 + c0;
        float* dst = sB + r * 136 + c0;
        cpa_ca(dst, src);
        cpa_ca(dst + 4, src + 4);
    }
    CPA_COMMIT();

#pragma unroll
    for (int kc = 0; kc < 4; ++kc) {
        if (kc < 3) {
            int r = tid >> 4, c0 = (tid & 15) * 8;
            const float* src = W + (size_t)(kt * 128 + (kc + 1) * 32 + r) * 2048 + n0 + c0;
            float* dst = sB + ((kc + 1) & 1) * (32 * 136) + r * 136 + c0;
            cpa_ca(dst, src);
            cpa_ca(dst + 4, src + 4);
            CPA_COMMIT();
            CPA_WAIT(1);
        } else {
            CPA_WAIT(0);
        }
        __syncthreads();
        const float* sBb = sB + (kc & 1) * (32 * 136);
#pragma unroll
        for (int ks = 0; ks < 4; ++ks) {
            const int kb = kc * 32 + ks * 8;
            unsigned af[2][4];
#pragma unroll
            for (int mt = 0; mt < 2; ++mt) {
                int row = mg + mt * 16 + (lane >> 2);
                int k = kb + (lane & 3);
                af[mt][0] = fu(sA[row * 132 + k]);
                af[mt][1] = fu(sA[(row + 8) * 132 + k]);
                af[mt][2] = fu(sA[row * 132 + k + 4]);
                af[mt][3] = fu(sA[(row + 8) * 132 + k + 4]);
            }
#pragma unroll
            for (int nt = 0; nt < 4; ++nt) {
                int col = ng + nt * 8 + (lane >> 2);
                int rr = ks * 8 + (lane & 3);
                unsigned bf[2];
                bf[0] = fu(sBb[rr * 136 + col]);
                bf[1] = fu(sBb[(rr + 4) * 136 + col]);
                mma8(acc[0][nt], af[0], bf);
                mma8(acc[1][nt], af[1], bf);
            }
        }
        __syncthreads();
    }
    float* C = g_part + (size_t)kt * 262144 + n0;
#pragma unroll
    for (int mt = 0; mt < 2; ++mt)
#pragma unroll
        for (int nt = 0; nt < 4; ++nt) {
            int row = mg + mt * 16 + (lane >> 2);
            int col = ng + nt * 8 + (lane & 3) * 2;
            *(float2*)(C + (size_t)row * 2048 + col) = make_float2(acc[mt][nt][0], acc[mt][nt][1]);
            *(float2*)(C + (size_t)(row + 8) * 2048 + col) = make_float2(acc[mt][nt][2], acc[mt][nt][3]);
        }
}

// reduce split-K partials + LSTM pointwise. CTA r handles batch row r. 512 threads -> j=tid.
__device__ __forceinline__ void lstm_point(int nsplit, const float* __restrict__ b,
                                           float* cst, float* dst1, int ld1,
                                           float* dst2, int ld2) {
    const int r = blockIdx.x;
    const int j = threadIdx.x;
    float gi = b[j], gf = b[512 + j], gc = b[1024 + j], go = b[1536 + j];
    for (int s = 0; s < nsplit; ++s) {
        const float* p = g_part + (size_t)s * 262144 + (size_t)r * 2048;
        gi += __ldcg(p + j);
        gf += __ldcg(p + 512 + j);
        gc += __ldcg(p + 1024 + j);
        go += __ldcg(p + 1536 + j);
    }
    float iv = sigmf(gi), fv = sigmf(gf), ov = sigmf(go), cg = tanhf(gc);
    float c2 = fv * cst[r * 512 + j] + iv * cg;
    cst[r * 512 + j] = c2;
    float h = tf32r(ov * tanhf(c2));
    dst1[r * ld1 + j] = h;
    dst2[r * ld2 + j] = h;
}

// ---------------- init ----------------
__global__ void init_kernel(const float* __restrict__ x, const float* __restrict__ e0W,
                            const float* __restrict__ e0U, const float* __restrict__ e1W,
                            const float* __restrict__ e1U, const float* __restrict__ muW,
                            const float* __restrict__ sgW, const float* __restrict__ d0W,
                            const float* __restrict__ d0U, const float* __restrict__ d1W,
                            const float* __restrict__ d1U, const float* __restrict__ oW) {
    size_t id = (size_t)blockIdx.x * blockDim.x + threadIdx.x;
    size_t st = (size_t)gridDim.x * blockDim.x;
    for (size_t i = id; i < 768u * 2048u; i += st) {
        int r = (int)(i >> 11), n = (int)(i & 2047);
        float v;
        if (r < 128) v = e0W[(size_t)r * 2048 + n] + e0W[(size_t)(r + 128) * 2048 + n];
        else if (r < 256) v = -e0W[(size_t)r * 2048 + n];
        else v = e0U[(size_t)(r - 256) * 2048 + n];
        g_Wc0[i] = tf32r(v);
    }
    for (size_t i = id; i < 1024u * 2048u; i += st) {
        int r = (int)(i >> 11), n = (int)(i & 2047);
        float v = (r < 512) ? e1W[(size_t)r * 2048 + n] : e1U[(size_t)(r - 512) * 2048 + n];
        g_Wc1[i] = tf32r(v);
    }
    for (size_t i = id; i < 640u * 2048u; i += st) {
        int r = (int)(i >> 11), n = (int)(i & 2047);
        float v = 0.f;
        if (r < 64) v = d0W[(size_t)r * 2048 + n];
        else if (r < 576) v = d0U[(size_t)(r - 64) * 2048 + n];
        g_Wc2[i] = tf32r(v);
    }
    for (size_t i = id; i < 1024u * 2048u; i += st) {
        int r = (int)(i >> 11), n = (int)(i & 2047);
        float v = (r < 512) ? d1W[(size_t)r * 2048 + n] : d1U[(size_t)(r - 512) * 2048 + n];
        g_Wc3[i] = tf32r(v);
    }
    // transposed small-layer weights, full fp32
    for (size_t i = id; i < 128u * 512u; i += st) {
        int c = (int)(i >> 9), k = (int)(i & 511);
        g_WmsT[i] = (c < 64) ? muW[(size_t)k * 64 + c] : sgW[(size_t)k * 64 + (c - 64)];
        g_WoutT[i] = oW[(size_t)k * 128 + c];
    }
    // A_enc0: [xt(t=0) | sigmoid(0)=0.5 | eh0=0]
    for (size_t i = id; i < 128u * 768u; i += st) {
        int r = (int)(i / 768), c = (int)(i % 768);
        float v;
        if (c < 128) v = tf32r(x[(size_t)r * TT * 128 + c]);
        else if (c < 256) v = 0.5f;
        else v = 0.f;
        g_Ae0[i] = v;
    }
    for (size_t i = id; i < 128u * 1024u; i += st) { g_Ae1[i] = 0.f; g_Ad1[i] = 0.f; }
    for (size_t i = id; i < 128u * 640u; i += st) g_Ad0[i] = 0.f;
    for (size_t i = id; i < 128u * 512u; i += st) {
        g_ec0[i] = 0.f; g_ec1[i] = 0.f; g_dc0[i] = 0.f; g_dc1[i] = 0.f;
        g_eh1[i] = 0.f; g_dh1[i] = 0.f;
    }
    if (id == 0) { g_barctr = 0; }
}

// ---------------- persistent kernel ----------------
__global__ void __launch_bounds__(512, 1)
vae_kernel(const float* __restrict__ x, const float* __restrict__ eps,
           const float* __restrict__ e0b, const float* __restrict__ e1b,
           const float* __restrict__ mub, const float* __restrict__ sgb,
           const float* __restrict__ d0b, const float* __restrict__ d1b,
           const float* __restrict__ ob, float* __restrict__ out) {
    extern __shared__ float sm[];
    unsigned lgen = 0;
    const int cta = blockIdx.x;
    const int tid = threadIdx.x;
    const int lane = tid & 31;
    const int wid = tid >> 5;

    float* dec_o = out;                  // [B,T,D]
    float* sig_o = out + 4194304;        // [T,B,Z]
    float* mu_o  = out + 6291456;
    float* ls_o  = out + 8388608;
    float* z_o   = out + 10485760;

    for (int t = 0; t < TT; ++t) {
        // P0: enc0 GEMM (96 units)
        if (cta < 96) gemm_tile(g_Ae0, 768, g_Wc0, cta >> 4, (cta & 15) << 7, sm);
        gbar(lgen);
        // P1: reduce(6)+LSTM enc0 -> eh0
        lstm_point(6, e0b, g_ec0, g_Ae1, 1024, g_Ae0 + 256, 768);
        gbar(lgen);
        // P2: enc1 GEMM (128 units)
        gemm_tile(g_Ae1, 1024, g_Wc1, cta >> 4, (cta & 15) << 7, sm);
        gbar(lgen);
        // P3: reduce(8)+LSTM enc1 -> eh1
        lstm_point(8, e1b, g_ec1, g_eh1, 512, g_Ae1 + 512, 1024);
        gbar(lgen);
        // P4: mu/sig FFMA + z-sample (all CTAs; 16-row x 8-col blocks, quad split-K)
        {
            const int rg = cta >> 4, g = cta & 15;
            const int ksub = lane & 3, cl = lane >> 2;   // cl 0..7
            const int r = rg * 16 + wid;                 // one row per warp
            const int cidx = g * 4 + (cl & 3);           // 0..63
            const bool is_sig = cl >= 4;
            const int colw = is_sig ? 64 + cidx : cidx;
            const float* e = g_eh1 + r * 512 + ksub * 128;
            const float* w = g_WmsT + colw * 512 + ksub * 128;
            float acc = 0.f;
#pragma unroll 8
            for (int i = 0; i < 32; ++i) {
                float4 ev = __ldcg((const float4*)(e + i * 4));
                float4 wv = __ldg((const float4*)(w + i * 4));
                acc = fmaf(ev.x, wv.x, acc);
                acc = fmaf(ev.y, wv.y, acc);
                acc = fmaf(ev.z, wv.z, acc);
                acc = fmaf(ev.w, wv.w, acc);
            }
            acc += __shfl_xor_sync(0xffffffffu, acc, 1);
            acc += __shfl_xor_sync(0xffffffffu, acc, 2);
            float other = __shfl_xor_sync(0xffffffffu, acc, 16);
            if (!is_sig && ksub == 0) {
                float mu = acc + mub[cidx];
                float ls = other + sgb[cidx];
                float sg = expf(ls);
                size_t o = ((size_t)t * 128 + r) * 64 + cidx;
                float z = mu + sg * eps[o];
                mu_o[o] = mu; ls_o[o] = ls; sig_o[o] = sg; z_o[o] = z;
                g_Ad0[r * 640 + cidx] = tf32r(z);
            }
        }
        gbar(lgen);
        // P5: dec0 GEMM (80 units)
        if (cta < 80) gemm_tile(g_Ad0, 640, g_Wc2, cta >> 4, (cta & 15) << 7, sm);
        gbar(lgen);
        // P6: reduce(5)+LSTM dec0 -> dh0
        lstm_point(5, d0b, g_dc0, g_Ad1, 1024, g_Ad0 + 64, 640);
        gbar(lgen);
        // P7: dec1 GEMM (128 units)
        gemm_tile(g_Ad1, 1024, g_Wc3, cta >> 4, (cta & 15) << 7, sm);
        gbar(lgen);
        // P8: reduce(8)+LSTM dec1 -> dh1
        lstm_point(8, d1b, g_dc1, g_dh1, 512, g_Ad1 + 512, 1024);
        gbar(lgen);
        // P9: out dense FFMA + sigmoid + outputs + next-step A prep (all CTAs)
        {
            const int rg = cta >> 4, g = cta & 15;
            const int ksub = lane & 3, cl = lane >> 2;
            const int r = rg * 16 + wid;
            const int col = g * 8 + cl;                  // 0..127
            const float* e = g_dh1 + r * 512 + ksub * 128;
            const float* w = g_WoutT + col * 512 + ksub * 128;
            float acc = 0.f;
#pragma unroll 8
            for (int i = 0; i < 32; ++i) {
                float4 ev = __ldcg((const float4*)(e + i * 4));
                float4 wv = __ldg((const float4*)(w + i * 4));
                acc = fmaf(ev.x, wv.x, acc);
                acc = fmaf(ev.y, wv.y, acc);
                acc = fmaf(ev.z, wv.z, acc);
                acc = fmaf(ev.w, wv.w, acc);
            }
            acc += __shfl_xor_sync(0xffffffffu, acc, 1);
            acc += __shfl_xor_sync(0xffffffffu, acc, 2);
            if (ksub == 0) {
                float cv = sigmf(acc + ob[col]);
                dec_o[((size_t)r * TT + t) * 128 + col] = cv;
                g_Ae0[r * 768 + 128 + col] = tf32r(sigmf(cv));
                if (t + 1 < TT)
                    g_Ae0[r * 768 + col] = tf32r(x[((size_t)r * TT + (t + 1)) * 128 + col]);
            }
        }
        gbar(lgen);
    }
}

extern "C" void kernel_launch(void* const* d_in, const int* in_sizes, int n_in,
                              void* d_out, int out_size) {
    const float* x = (const float*)d_in[0];
    const float* eps = (const float*)d_in[1];
    const int smem_bytes = (128 * 132 + 2 * 32 * 136) * 4;  // 102400
    cudaFuncSetAttribute(vae_kernel, cudaFuncAttributeMaxDynamicSharedMemorySize, smem_bytes);
    init_kernel<<<512, 256>>>(x, (const float*)d_in[2], (const float*)d_in[3],
                              (const float*)d_in[5], (const float*)d_in[6],
                              (const float*)d_in[8], (const float*)d_in[10],
                              (const float*)d_in[12], (const float*)d_in[13],
                              (const float*)d_in[15], (const float*)d_in[16],
                              (const float*)d_in[18]);
    vae_kernel<<<128, 512, smem_bytes>>>(x, eps, (const float*)d_in[4], (const float*)d_in[7],
                                         (const float*)d_in[9], (const float*)d_in[11],
                                         (const float*)d_in[14], (const float*)d_in[17],
                                         (const float*)d_in[19], (float*)d_out);
}